// round 7
// baseline (speedup 1.0000x reference)
#include <cuda_runtime.h>

// ---------------------------------------------------------------------------
// WideDeep wide-side sequential SGD, restructured:
//   * lazy decay folded into scaled representation  c = w * f^(-dt)
//     (gather at step q: true = c*f^q;  SGD: c += -LR*g*f^(-q))
//   * touched weights (<=65536 of 16.7M) hash-compacted into a 131072-slot
//     table: 512 KB of values -> fully L2-resident (~234 cyc, not ~577 HBM)
//   * intra-sample duplicate multiplicities precomputed -> plain stores,
//     no atomics in the sequential loop
//   * adjacent-sample conflict flags precomputed -> distance-1 speculative
//     gather prefetch hides load latency on ~all 1023 steps
//   * sequential kernel: 1 block x 32 threads, warp-synchronous shfl reduce
//     (redux.sync.add.f32 rejected: harness PTX stage targets compute_103,
//      which lacks the sm_100a-family f32 redux)
// ---------------------------------------------------------------------------

#define D_SIZE    16777216
#define B_N       1024
#define F_N       64
#define NOCC      (B_N * F_N)          // 65536 occurrences
#define LR_W      0.05f
#define ONE_MINUS 0.999999f            // 1 - L2_DECAY
#define TBL_BITS  17
#define TBL_SIZE  (1 << TBL_BITS)      // 131072 slots, load factor 0.5
#define TBL_MASK  (TBL_SIZE - 1)

// Scratch (no cudaMalloc allowed): ~1.3 MB of __device__ globals.
__device__ int   g_key[TBL_SIZE];
__device__ float g_val[TBL_SIZE];
__device__ int   g_slot[NOCC];
__device__ float g_mult[NOCC];
__device__ int   g_conflict[B_N];

__device__ __forceinline__ unsigned hash_idx(unsigned x) {
    x *= 2654435761u;
    x ^= x >> 15;
    return x & TBL_MASK;
}

// Warp sum: 5-level butterfly (portable across the compute_103 PTX stage).
__device__ __forceinline__ float warp_sum(float v) {
    #pragma unroll
    for (int o = 16; o; o >>= 1) v += __shfl_xor_sync(0xffffffffu, v, o);
    return v;
}

// ---- pass 1: clear hash keys + conflict flags -----------------------------
__global__ void k_clear() {
    int i = blockIdx.x * blockDim.x + threadIdx.x;
    if (i < TBL_SIZE) g_key[i] = -1;
    if (i < B_N)      g_conflict[i] = 0;
}

// ---- pass 2: insert indices, assign slots, init scaled values -------------
__global__ void k_insert(const int* __restrict__ xw,
                         const float* __restrict__ w,
                         const int* __restrict__ dtimes) {
    int e = blockIdx.x * blockDim.x + threadIdx.x;
    if (e >= NOCC) return;
    int idx = xw[e];
    unsigned h = hash_idx((unsigned)idx);
    for (;;) {
        int old = atomicCAS(&g_key[h], -1, idx);
        if (old == -1) {
            // winner initializes the scaled value  c = w * f^(-dt0)
            float dtf = (float)dtimes[idx];
            g_val[h] = w[idx] * powf(ONE_MINUS, -dtf);
            g_slot[e] = (int)h;
            return;
        } else if (old == idx) {
            g_slot[e] = (int)h;
            return;
        }
        h = (h + 1) & TBL_MASK;
    }
}

// ---- pass 3: duplicate multiplicities + adjacent-sample conflict flags ----
__global__ void k_meta() {
    int e = blockIdx.x * blockDim.x + threadIdx.x;
    if (e >= NOCC) return;
    int j = e >> 6;
    int f = e & 63;
    int s = g_slot[e];
    int base = j << 6;

    int count = 0, first = 64;
    #pragma unroll 8
    for (int f2 = 0; f2 < F_N; f2++) {
        if (g_slot[base + f2] == s) {
            count++;
            if (f2 < first) first = f2;
        }
    }
    // only the first occurrence writes, with multiplicity = count
    g_mult[e] = (first == f) ? (float)count : 0.0f;

    // conflict[j] = sample j shares a slot with sample j-1
    if (j > 0) {
        int pb = (j - 1) << 6;
        bool c = false;
        #pragma unroll 8
        for (int f2 = 0; f2 < F_N; f2++) c |= (g_slot[pb + f2] == s);
        if (c) g_conflict[j] = 1;   // benign write race: everyone writes 1
    }
}

// ---- pass 4: sequential loop, 1 warp ---------------------------------------
__global__ void __launch_bounds__(32, 1)
k_seq(const float* __restrict__ y,
      const float* __restrict__ b_in,
      float* __restrict__ out) {
    const int lane = threadIdx.x;
    float b = b_in[0];

    const float f1    = ONE_MINUS;
    const float finv1 = 1.0f / ONE_MINUS;
    float fq = 1.0f, finv = 1.0f;      // f^q and f^(-q), q = step index

    // prime the pipeline: sample 0 gathers (no prior writes exist)
    int s0 = g_slot[lane];
    int s1 = g_slot[32 + lane];
    float v0 = __ldcg(&g_val[s0]);
    float v1 = __ldcg(&g_val[s1]);

    #pragma unroll 1
    for (int j = 0; j < B_N; j++) {
        // --- speculative prefetch of step j+1 (issued before step-j stores);
        //     safe iff sample j+1 shares no slot with sample j (cf==0).
        //     Overlaps with samples <= j-1 are ordered by the prior syncwarp.
        int ns0 = 0, ns1 = 0;
        float nv0 = 0.0f, nv1 = 0.0f;
        const bool notlast = (j < B_N - 1);
        int cf = 1;
        if (notlast) {
            int nb = (j + 1) << 6;
            ns0 = g_slot[nb + lane];
            ns1 = g_slot[nb + 32 + lane];
            cf  = g_conflict[j + 1];
            if (!cf) {
                nv0 = __ldcg(&g_val[ns0]);
                nv1 = __ldcg(&g_val[ns1]);
            }
        }

        // per-step constants loaded up front (independent of the reduce chain)
        const float yj = y[j];
        const int eb = j << 6;
        const float m0 = g_mult[eb + lane];
        const float m1 = g_mult[eb + 32 + lane];

        // --- reduce 64 scaled values across the warp ---
        float s = warp_sum(v0 + v1);

        // --- forward: z, sigmoid, gradient ---
        float z = fminf(fmaxf(fmaf(s, fq, b), -35.0f), 35.0f);
        float p = 1.0f / (1.0f + __expf(-z));
        float g = p - yj;
        if (lane == 0) out[j] = p;
        b -= LR_W * g;

        // --- update: first-occurrence lanes write  v + k * (-LR*g*f^-q) ---
        const float delta = -LR_W * g * finv;
        if (m0 != 0.0f) __stcg(&g_val[s0], fmaf(m0, delta, v0));
        if (m1 != 0.0f) __stcg(&g_val[s1], fmaf(m1, delta, v1));
        __syncwarp();   // orders this step's stores before all later gathers

        // conflicting step (rare, ~2.4e-4/step): gather after ordering
        if (notlast && cf) {
            nv0 = __ldcg(&g_val[ns0]);
            nv1 = __ldcg(&g_val[ns1]);
        }

        s0 = ns0; s1 = ns1; v0 = nv0; v1 = nv1;
        fq *= f1; finv *= finv1;
    }
}

// ---------------------------------------------------------------------------
extern "C" void kernel_launch(void* const* d_in, const int* in_sizes, int n_in,
                              void* d_out, int out_size) {
    // identify inputs by element count
    // (metadata order: X_w_indices[65536], X_d[3072], y[1024], w[16777216],
    //  b[1], decay_times[16777216])
    const int*   xw = nullptr;
    const float* y  = nullptr;
    const float* w  = nullptr;
    const float* b  = nullptr;
    const int*   dtimes = nullptr;
    int bigCount = 0;
    for (int i = 0; i < n_in; i++) {
        int sz = in_sizes[i];
        if      (sz == NOCC)     xw = (const int*)d_in[i];
        else if (sz == B_N)      y  = (const float*)d_in[i];
        else if (sz == 1)        b  = (const float*)d_in[i];
        else if (sz == D_SIZE) {
            if (bigCount++ == 0) w  = (const float*)d_in[i];
            else                 dtimes = (const int*)d_in[i];
        }
        // X_d (size 3072) is unused by the forward pass
    }

    k_clear <<<TBL_SIZE / 256, 256>>>();
    k_insert<<<NOCC / 256,     256>>>(xw, w, dtimes);
    k_meta  <<<NOCC / 256,     256>>>();
    k_seq   <<<1, 32>>>(y, b, (float*)d_out);
}

// round 8
// speedup vs baseline: 4.6908x; 4.6908x over previous
#include <cuda_runtime.h>

// ---------------------------------------------------------------------------
// WideDeep wide-side sequential SGD — interaction-factored formulation.
//
// Key identity (scaled weights c = w * f^(-dt), f = 1-L2):
//   S_scaled(j) = S0_j + sum_{k<j} K_{k,j} * g_k
//   K_{k,j}     = -LR * f^(-k) * (#occurrence pairs sharing an index, k vs j)
//   z_j = S_scaled(j)*f^j + b_j ;  p = sigmoid(clip(z)) ;  b -= LR*(p-y)
//
// The weight array is never written. All index-sharing sample pairs
// (expected ~128 for this dataset) are found in a parallel pre-pass via a
// hash-chained grouping of the 65536 occurrences; the sequential part is a
// single-thread scalar recurrence (~60 dependent cycles/step).
// ---------------------------------------------------------------------------

#define D_SIZE    16777216
#define B_N       1024
#define F_N       64
#define NOCC      (B_N * F_N)          // 65536 occurrences
#define LR_W      0.05f
#define ONE_MINUS 0.999999f            // 1 - L2_DECAY
#define TBL_BITS  17
#define TBL_SIZE  (1 << TBL_BITS)
#define TBL_MASK  (TBL_SIZE - 1)
#define CAP       (1 << 20)            // interaction capacity (huge margin)

// Scratch: __device__ globals (no cudaMalloc allowed).
__device__ int   g_head[TBL_SIZE];     // hash-bucket chain heads
__device__ int   g_next[NOCC];         // occurrence chain links
__device__ float g_S0[B_N];            // per-sample scaled base sum
__device__ float g_fq[B_N];            // f^j
__device__ float g_fqinv[B_N];         // f^(-j)
__device__ int   g_rowcnt[B_N];        // interactions per later-sample b
__device__ int   g_rowptr[B_N + 1];    // CSR row pointers
__device__ int   g_rowfill[B_N];       // scatter cursors
__device__ int   g_ninter;             // total interactions
__device__ int   g_csr_a[CAP];         // earlier sample index a
__device__ float g_csr_k[CAP];         // coefficient K = -LR * f^(-a)

__device__ __forceinline__ unsigned hash_idx(unsigned x) {
    x *= 2654435761u;
    x ^= x >> 15;
    return x & TBL_MASK;
}

// ---- init: clear heads, counters, S0, and the f^j tables -------------------
__global__ void k_init() {
    int i = blockIdx.x * blockDim.x + threadIdx.x;
    if (i < TBL_SIZE) g_head[i] = -1;
    if (i < B_N) {
        g_rowcnt[i] = 0;
        g_S0[i]     = 0.0f;
        float fj = (float)i;
        g_fq[i]    = powf(ONE_MINUS,  fj);
        g_fqinv[i] = powf(ONE_MINUS, -fj);
    }
    if (i == 0) g_ninter = 0;
}

// ---- gather: scaled base sums + hash-chain occurrences by index ------------
__global__ void k_gather(const int* __restrict__ xw,
                         const float* __restrict__ w,
                         const int* __restrict__ dtimes) {
    int e = blockIdx.x * blockDim.x + threadIdx.x;   // occurrence id
    if (e >= NOCC) return;
    int idx = xw[e];

    // scaled contribution  c = w * f^(-dt)
    float c = w[idx] * powf(ONE_MINUS, -(float)dtimes[idx]);

    // half-sample (32 consecutive occurrences) warp reduce, one atomic per warp
    float s = c;
    #pragma unroll
    for (int o = 16; o; o >>= 1) s += __shfl_xor_sync(0xffffffffu, s, o);
    if ((threadIdx.x & 31) == 0) atomicAdd(&g_S0[e >> 6], s);

    // chain insert (grouping by raw index; collisions resolved at walk time)
    g_next[e] = atomicExch(&g_head[hash_idx((unsigned)idx)], e);
}

// ---- count: per-(later sample b) interaction counts ------------------------
__global__ void k_count(const int* __restrict__ xw) {
    int e = blockIdx.x * blockDim.x + threadIdx.x;
    if (e >= NOCC) return;
    int idx = xw[e];
    int b   = e >> 6;
    int cnt = 0;
    for (int e2 = g_head[hash_idx((unsigned)idx)]; e2 >= 0; e2 = g_next[e2])
        if (xw[e2] == idx && (e2 >> 6) < b) cnt++;
    if (cnt) atomicAdd(&g_rowcnt[b], cnt);
}

// ---- scan: exclusive prefix over 1024 row counts ---------------------------
__global__ void k_scan() {
    __shared__ int sh[B_N];
    int t = threadIdx.x;
    sh[t] = g_rowcnt[t];
    __syncthreads();
    #pragma unroll
    for (int off = 1; off < B_N; off <<= 1) {
        int v = (t >= off) ? sh[t - off] : 0;
        __syncthreads();
        sh[t] += v;
        __syncthreads();
    }
    g_rowptr[t + 1] = sh[t];                 // inclusive -> shifted
    int excl = sh[t] - g_rowcnt[t];
    g_rowfill[t] = excl;
    if (t == 0) { g_rowptr[0] = 0; g_ninter = sh[B_N - 1]; }
}

// ---- fill: scatter interaction entries into CSR ----------------------------
__global__ void k_fill(const int* __restrict__ xw) {
    int e = blockIdx.x * blockDim.x + threadIdx.x;
    if (e >= NOCC) return;
    int idx = xw[e];
    int b   = e >> 6;
    for (int e2 = g_head[hash_idx((unsigned)idx)]; e2 >= 0; e2 = g_next[e2]) {
        int a = e2 >> 6;
        if (xw[e2] == idx && a < b) {
            int pos = atomicAdd(&g_rowfill[b], 1);
            if (pos < CAP) {
                g_csr_a[pos] = a;
                g_csr_k[pos] = -LR_W * g_fqinv[a];
            }
        }
    }
}

// ---- scalar sequential recurrence: 1 warp (31 lanes preload, lane 0 runs) --
__global__ void __launch_bounds__(32, 1)
k_scalar(const float* __restrict__ y,
         const float* __restrict__ b_in,
         float* __restrict__ out) {
    __shared__ float sSp[B_N];     // S0[j] * f^j   (pre-multiplied base logit)
    __shared__ float sFq[B_N];     // f^j           (for rare corr terms)
    __shared__ float sY [B_N];
    __shared__ float sG [B_N];     // gradient history
    __shared__ int   sRp[B_N + 1];

    const int lane = threadIdx.x;
    // parallel preload into smem (coalesced, latency hidden across 32 lanes)
    for (int j = lane; j < B_N; j += 32) {
        float fq = g_fq[j];
        sSp[j] = g_S0[j] * fq;
        sFq[j] = fq;
        sY [j] = y[j];
        sRp[j] = g_rowptr[j];
    }
    if (lane == 0) sRp[B_N] = g_rowptr[B_N];
    __syncwarp();

    if (lane != 0) return;

    float b = b_in[0];
    int r = sRp[0];
    #pragma unroll 4
    for (int j = 0; j < B_N; j++) {
        int rEnd = sRp[j + 1];
        float z;
        if (r == rEnd) {                       // ~99.99% of steps
            z = sSp[j] + b;
        } else {                               // rare: apply collision corr
            float corr = 0.0f;
            for (; r < rEnd; r++)
                corr += g_csr_k[r] * sG[g_csr_a[r]];
            z = fmaf(corr, sFq[j], sSp[j] + b);
        }
        z = fminf(fmaxf(z, -35.0f), 35.0f);
        float p = 1.0f / (1.0f + __expf(-z));
        float g = p - sY[j];
        out[j] = p;
        sG[j]  = g;
        b -= LR_W * g;
    }
}

// ---------------------------------------------------------------------------
extern "C" void kernel_launch(void* const* d_in, const int* in_sizes, int n_in,
                              void* d_out, int out_size) {
    // metadata order: X_w_indices[65536], X_d[3072], y[1024], w[16777216],
    //                 b[1], decay_times[16777216]
    const int*   xw = nullptr;
    const float* y  = nullptr;
    const float* w  = nullptr;
    const float* b  = nullptr;
    const int*   dtimes = nullptr;
    int bigCount = 0;
    for (int i = 0; i < n_in; i++) {
        int sz = in_sizes[i];
        if      (sz == NOCC)     xw = (const int*)d_in[i];
        else if (sz == B_N)      y  = (const float*)d_in[i];
        else if (sz == 1)        b  = (const float*)d_in[i];
        else if (sz == D_SIZE) {
            if (bigCount++ == 0) w  = (const float*)d_in[i];
            else                 dtimes = (const int*)d_in[i];
        }
        // X_d (3072) unused by the wide forward pass
    }

    k_init  <<<TBL_SIZE / 256, 256>>>();
    k_gather<<<NOCC / 256,     256>>>(xw, w, dtimes);
    k_count <<<NOCC / 256,     256>>>(xw);
    k_scan  <<<1, B_N>>>();
    k_fill  <<<NOCC / 256,     256>>>(xw);
    k_scalar<<<1, 32>>>(y, b, (float*)d_out);
}

// round 9
// speedup vs baseline: 5.7992x; 1.2363x over previous
#include <cuda_runtime.h>

// ---------------------------------------------------------------------------
// WideDeep wide-side sequential SGD — interaction-factored formulation, v2.
//
// Identity (scaled weights c = w * f^(-dt), f = 1-L2):
//   z_j = S0_j*f^j + f^j * sum_{k<j} (-LR*f^(-k)) * n_pairs(k,j) * g_k + b_j
//   p_j = sigmoid(z_j);  g_j = p_j - y_j;  b -= LR*g_j
// The weight array is never written; cross-sample couplings (expected ~128
// entries for this dataset) are harvested in parallel into per-row slot
// lists. The sequential part is a single-thread scalar recurrence with a
// ~44-cycle dependent chain:  fma -> ex2 -> add -> rcp -> fma.
// ---------------------------------------------------------------------------

#define D_SIZE    16777216
#define B_N       1024
#define F_N       64
#define NOCC      (B_N * F_N)          // 65536 occurrences
#define LR_W      0.05f
#define LN_F      1.0000005e-6f        // -ln(1 - 1e-6)
#define LOG2E     1.4426950408889634f
#define TBL_BITS  17
#define TBL_SIZE  (1 << TBL_BITS)
#define TBL_MASK  (TBL_SIZE - 1)
#define ROW_CAP   64                   // interaction slots per later-sample

// Scratch: __device__ globals (no cudaMalloc allowed).
__device__ int   g_head[TBL_SIZE];     // hash-bucket chain heads
__device__ int   g_next[NOCC];         // occurrence chain links
__device__ float g_S0[B_N];            // per-sample scaled base sum
__device__ int   g_rcnt[B_N];          // interactions per later-sample b
__device__ int   g_ra[B_N * ROW_CAP];  // earlier sample index a
__device__ float g_rk[B_N * ROW_CAP];  // coefficient -LR * f^(-a)

__device__ __forceinline__ unsigned hash_idx(unsigned x) {
    x *= 2654435761u;
    x ^= x >> 15;
    return x & TBL_MASK;
}

__device__ __forceinline__ float ex2_approx(float x) {
    float r;
    asm("ex2.approx.ftz.f32 %0, %1;" : "=f"(r) : "f"(x));
    return r;
}
__device__ __forceinline__ float rcp_approx(float x) {
    float r;
    asm("rcp.approx.ftz.f32 %0, %1;" : "=f"(r) : "f"(x));
    return r;
}

// ---- pass 1: clear chain heads, base sums, row counters --------------------
__global__ void k_init() {
    int i = blockIdx.x * blockDim.x + threadIdx.x;
    if (i < TBL_SIZE) g_head[i] = -1;
    if (i < B_N) { g_S0[i] = 0.0f; g_rcnt[i] = 0; }
}

// ---- pass 2: scaled base sums + hash-chain occurrences by index ------------
__global__ void k_gather(const int* __restrict__ xw,
                         const float* __restrict__ w,
                         const int* __restrict__ dtimes) {
    int e = blockIdx.x * blockDim.x + threadIdx.x;   // occurrence id
    if (e >= NOCC) return;
    int idx = xw[e];

    // scaled contribution  c = w * f^(-dt) = w * exp(dt * ln(1/f))
    float c = w[idx] * __expf((float)dtimes[idx] * LN_F);

    // 32 consecutive occurrences = half a sample: warp reduce, 1 atomic/warp
    float s = c;
    #pragma unroll
    for (int o = 16; o; o >>= 1) s += __shfl_xor_sync(0xffffffffu, s, o);
    if ((threadIdx.x & 31) == 0) atomicAdd(&g_S0[e >> 6], s);

    // chain insert (grouped by hashed index; collisions filtered at walk)
    g_next[e] = atomicExch(&g_head[hash_idx((unsigned)idx)], e);
}

// ---- pass 3: harvest cross-sample couplings into per-row slot lists --------
__global__ void k_pairs(const int* __restrict__ xw) {
    int e = blockIdx.x * blockDim.x + threadIdx.x;
    if (e >= NOCC) return;
    int idx = xw[e];
    int b   = e >> 6;
    for (int e2 = g_head[hash_idx((unsigned)idx)]; e2 >= 0; e2 = g_next[e2]) {
        int a = e2 >> 6;
        if (a < b && xw[e2] == idx) {
            int pos = atomicAdd(&g_rcnt[b], 1);
            if (pos < ROW_CAP) {
                g_ra[b * ROW_CAP + pos] = a;
                g_rk[b * ROW_CAP + pos] = -LR_W * __expf((float)a * LN_F);
            }
        }
    }
}

// ---- pass 4: scalar recurrence (1024 threads preload, thread 0 runs) -------
__global__ void __launch_bounds__(B_N, 1)
k_scalar(const float* __restrict__ y,
         const float* __restrict__ b_in,
         float* __restrict__ out) {
    __shared__ float sA  [B_N];    // -log2e * S0[j] * f^j
    __shared__ float sBy [B_N];    // LR * y[j]
    __shared__ float sY  [B_N];
    __shared__ float sFq [B_N];    // f^j (rare corr path)
    __shared__ float sG  [B_N];    // gradient history (rare corr path)
    __shared__ int   sCnt[B_N];

    const int j = threadIdx.x;
    {
        float fq = __expf(-(float)j * LN_F);     // f^j
        float yj = y[j];
        sA  [j] = -LOG2E * (g_S0[j] * fq);
        sBy [j] = LR_W * yj;
        sY  [j] = yj;
        sFq [j] = fq;
        sCnt[j] = g_rcnt[j];
    }
    __syncthreads();
    if (j != 0) return;

    float b = b_in[0];
    #pragma unroll 4
    for (int i = 0; i < B_N; i++) {
        float A = sA[i];
        if (sCnt[i]) {                    // rare (~1e-4/step): apply coupling
            float corr = 0.0f;
            int n = sCnt[i];
            for (int r = 0; r < n; r++)
                corr += g_rk[i * ROW_CAP + r] * sG[g_ra[i * ROW_CAP + r]];
            A -= LOG2E * corr * sFq[i];
        }
        // p = sigmoid(z), z = -(A + b*? )... chain: fma -> ex2 -> add -> rcp
        float t = fmaf(b, -LOG2E, A);     // t = -z*log2e
        float e = ex2_approx(t);          // e = exp(-z); saturates = clip
        float p = rcp_approx(1.0f + e);
        out[i] = p;
        sG[i]  = p - sY[i];
        b = fmaf(-LR_W, p, b + sBy[i]);   // b + LR*y computed off-chain
    }
}

// ---------------------------------------------------------------------------
extern "C" void kernel_launch(void* const* d_in, const int* in_sizes, int n_in,
                              void* d_out, int out_size) {
    // metadata order: X_w_indices[65536], X_d[3072], y[1024], w[16777216],
    //                 b[1], decay_times[16777216]
    const int*   xw = nullptr;
    const float* y  = nullptr;
    const float* w  = nullptr;
    const float* b  = nullptr;
    const int*   dtimes = nullptr;
    int bigCount = 0;
    for (int i = 0; i < n_in; i++) {
        int sz = in_sizes[i];
        if      (sz == NOCC)     xw = (const int*)d_in[i];
        else if (sz == B_N)      y  = (const float*)d_in[i];
        else if (sz == 1)        b  = (const float*)d_in[i];
        else if (sz == D_SIZE) {
            if (bigCount++ == 0) w  = (const float*)d_in[i];
            else                 dtimes = (const int*)d_in[i];
        }
        // X_d (3072) unused by the wide forward pass
    }

    k_init  <<<TBL_SIZE / 256, 256>>>();
    k_gather<<<NOCC / 256,     256>>>(xw, w, dtimes);
    k_pairs <<<NOCC / 256,     256>>>(xw);
    k_scalar<<<1, B_N>>>(y, b, (float*)d_out);
}

// round 10
// speedup vs baseline: 6.1307x; 1.0572x over previous
#include <cuda_runtime.h>

// ---------------------------------------------------------------------------
// WideDeep wide-side sequential SGD — interaction-factored formulation, v3.
//
//   z_j = S0_j*f^j + f^j * sum_{k<j} (-LR*f^(-k)) * n_pairs(k,j) * g_k + b_j
//   p_j = sigmoid(z_j) = 0.5*tanh(z_j/2)+0.5 ;  g_j = p_j - y_j ;  b -= LR*g_j
//
// v3 changes vs v2 (which ran ~270 cyc/step):
//   * correction rows compacted IN ORDER via warp ballot during preload;
//     the sequential loop runs branchless straight-line segments between
//     them (no BSSY/BSYNC in the hot body, LDS feeds pipeline ahead)
//   * sigmoid via single tanh.approx MUFU: dependent chain
//     fma(4) -> tanh(16) -> fma(4) -> fma(4) = 28 cyc/step
// ---------------------------------------------------------------------------

#define D_SIZE    16777216
#define B_N       1024
#define F_N       64
#define NOCC      (B_N * F_N)          // 65536 occurrences
#define LR_W      0.05f
#define LN_F      1.0000005e-6f        // -ln(1 - 1e-6)
#define TBL_BITS  17
#define TBL_SIZE  (1 << TBL_BITS)
#define TBL_MASK  (TBL_SIZE - 1)
#define ROW_CAP   64                   // interaction slots per later-sample

// Scratch: __device__ globals (no cudaMalloc allowed).
__device__ int   g_head[TBL_SIZE];     // hash-bucket chain heads
__device__ int   g_next[NOCC];         // occurrence chain links
__device__ float g_S0[B_N];            // per-sample scaled base sum
__device__ int   g_rcnt[B_N];          // interactions per later-sample b
__device__ int   g_ra[B_N * ROW_CAP];  // earlier sample index a
__device__ float g_rk[B_N * ROW_CAP];  // coefficient -LR * f^(-a)

__device__ __forceinline__ unsigned hash_idx(unsigned x) {
    x *= 2654435761u;
    x ^= x >> 15;
    return x & TBL_MASK;
}

// ---- pass 1: clear chain heads, base sums, row counters --------------------
__global__ void k_init() {
    int i = blockIdx.x * blockDim.x + threadIdx.x;
    if (i < TBL_SIZE) g_head[i] = -1;
    if (i < B_N) { g_S0[i] = 0.0f; g_rcnt[i] = 0; }
}

// ---- pass 2: scaled base sums + hash-chain occurrences by index ------------
__global__ void k_gather(const int* __restrict__ xw,
                         const float* __restrict__ w,
                         const int* __restrict__ dtimes) {
    int e = blockIdx.x * blockDim.x + threadIdx.x;   // occurrence id
    if (e >= NOCC) return;
    int idx = xw[e];

    // scaled contribution  c = w * f^(-dt) = w * exp(dt * ln(1/f))
    float c = w[idx] * __expf((float)dtimes[idx] * LN_F);

    // 32 consecutive occurrences = half a sample: warp reduce, 1 atomic/warp
    float s = c;
    #pragma unroll
    for (int o = 16; o; o >>= 1) s += __shfl_xor_sync(0xffffffffu, s, o);
    if ((threadIdx.x & 31) == 0) atomicAdd(&g_S0[e >> 6], s);

    // chain insert (grouped by hashed index; collisions filtered at walk)
    g_next[e] = atomicExch(&g_head[hash_idx((unsigned)idx)], e);
}

// ---- pass 3: harvest cross-sample couplings into per-row slot lists --------
__global__ void k_pairs(const int* __restrict__ xw) {
    int e = blockIdx.x * blockDim.x + threadIdx.x;
    if (e >= NOCC) return;
    int idx = xw[e];
    int b   = e >> 6;
    for (int e2 = g_head[hash_idx((unsigned)idx)]; e2 >= 0; e2 = g_next[e2]) {
        int a = e2 >> 6;
        if (a < b && xw[e2] == idx) {
            int pos = atomicAdd(&g_rcnt[b], 1);
            if (pos < ROW_CAP) {
                g_ra[b * ROW_CAP + pos] = a;
                g_rk[b * ROW_CAP + pos] = -LR_W * __expf((float)a * LN_F);
            }
        }
    }
}

// ---- pass 4: scalar recurrence, branchless segmented loop ------------------
__global__ void __launch_bounds__(B_N, 1)
k_scalar(const float* __restrict__ y,
         const float* __restrict__ b_in,
         float* __restrict__ out) {
    __shared__ float sAh [B_N];    // 0.5 * S0[j] * f^j
    __shared__ float sBy [B_N];    // LR * y[j]
    __shared__ float sY  [B_N];
    __shared__ float sFq [B_N];    // f^j (correction rows only)
    __shared__ float sG  [B_N];    // gradient history
    __shared__ int   sCnt[B_N];
    __shared__ int   sRows[B_N];   // ordered list of correction rows
    __shared__ int   sWoff[33];

    const int j    = threadIdx.x;
    const int wid  = j >> 5;
    const int lane = j & 31;

    // parallel preload + ordered compaction of correction rows
    float fq = __expf(-(float)j * LN_F);         // f^j
    float yj = y[j];
    sAh[j] = 0.5f * (g_S0[j] * fq);
    sBy[j] = LR_W * yj;
    sY [j] = yj;
    sFq[j] = fq;
    int cnt = g_rcnt[j];
    sCnt[j] = cnt;
    unsigned m = __ballot_sync(0xffffffffu, cnt > 0);
    if (lane == 0) sWoff[wid] = __popc(m);
    __syncthreads();
    if (j == 0) {
        int acc = 0;
        #pragma unroll
        for (int wq = 0; wq < 32; wq++) { int c = sWoff[wq]; sWoff[wq] = acc; acc += c; }
        sWoff[32] = acc;
    }
    __syncthreads();
    if (cnt > 0)
        sRows[sWoff[wid] + __popc(m & ((1u << lane) - 1u))] = j;
    __syncthreads();
    if (j != 0) return;

    const int nc = sWoff[32];
    float b = b_in[0];
    int i = 0, ci = 0;
    for (;;) {
        int stop = (ci < nc) ? sRows[ci] : B_N;
        // hot path: branchless straight-line body; chain = fma->tanh->fma->fma
        for (; i < stop; i++) {
            float t = fmaf(b, 0.5f, sAh[i]);                 // z/2
            float th; asm("tanh.approx.f32 %0, %1;" : "=f"(th) : "f"(t));
            float p = fmaf(0.5f, th, 0.5f);                  // sigmoid(z)
            out[i] = p;
            sG [i] = p - sY[i];
            b = fmaf(-LR_W, p, b + sBy[i]);                  // b+LR*y off-chain
        }
        if (i >= B_N) break;
        {   // correction row (rare): fold cross-sample coupling into z
            float corr = 0.0f;
            int n = sCnt[i]; if (n > ROW_CAP) n = ROW_CAP;
            int base = i * ROW_CAP;
            for (int r = 0; r < n; r++)
                corr += g_rk[base + r] * sG[g_ra[base + r]];
            float t = fmaf(b, 0.5f, fmaf(0.5f * sFq[i], corr, sAh[i]));
            float th; asm("tanh.approx.f32 %0, %1;" : "=f"(th) : "f"(t));
            float p = fmaf(0.5f, th, 0.5f);
            out[i] = p;
            sG [i] = p - sY[i];
            b = fmaf(-LR_W, p, b + sBy[i]);
            i++; ci++;
        }
    }
}

// ---------------------------------------------------------------------------
extern "C" void kernel_launch(void* const* d_in, const int* in_sizes, int n_in,
                              void* d_out, int out_size) {
    // metadata order: X_w_indices[65536], X_d[3072], y[1024], w[16777216],
    //                 b[1], decay_times[16777216]
    const int*   xw = nullptr;
    const float* y  = nullptr;
    const float* w  = nullptr;
    const float* b  = nullptr;
    const int*   dtimes = nullptr;
    int bigCount = 0;
    for (int i = 0; i < n_in; i++) {
        int sz = in_sizes[i];
        if      (sz == NOCC)     xw = (const int*)d_in[i];
        else if (sz == B_N)      y  = (const float*)d_in[i];
        else if (sz == 1)        b  = (const float*)d_in[i];
        else if (sz == D_SIZE) {
            if (bigCount++ == 0) w  = (const float*)d_in[i];
            else                 dtimes = (const int*)d_in[i];
        }
        // X_d (3072) unused by the wide forward pass
    }

    k_init  <<<TBL_SIZE / 256, 256>>>();
    k_gather<<<NOCC / 256,     256>>>(xw, w, dtimes);
    k_pairs <<<NOCC / 256,     256>>>(xw);
    k_scalar<<<1, B_N>>>(y, b, (float*)d_out);
}

// round 14
// speedup vs baseline: 6.7045x; 1.0936x over previous
#include <cuda_runtime.h>

// ---------------------------------------------------------------------------
// WideDeep wide-side sequential SGD — interaction-factored formulation, v5.
//
//   z_j = S0_j*f^j + f^j * sum_{k<j} (-LR*f^(-k)) * n_pairs(k,j) * g_k + b_j
//   p_j = sigmoid(z_j) = 0.5*tanh(z_j/2)+0.5 ;  g_j = p_j - y_j ;  b -= LR*g_j
//
// v5 = v4 with the carry-recurrence coefficients fixed:
//   t = z/2 ;  t_{i+1} = t_i + dAh_i - 0.5*LR*(p_i - y_i)
//            = t_i + [dAh_i - 0.0125*(1-2y_i)] - 0.0125*th_i
//   (v4 wrongly used 0.025 for the th/constant terms -> rel_err 0.48)
// Chain per hot iter: tanh(16) + fma(4) = 20 cyc; adds run parallel to MUFU.
// ---------------------------------------------------------------------------

#define D_SIZE    16777216
#define B_N       1024
#define F_N       64
#define NOCC      (B_N * F_N)          // 65536 occurrences
#define LR_W      0.05f
#define LN_F      1.0000005e-6f        // -ln(1 - 1e-6)
#define TBL_BITS  17
#define TBL_SIZE  (1 << TBL_BITS)
#define TBL_MASK  (TBL_SIZE - 1)
#define ROW_CAP   64                   // interaction slots per later-sample

// Scratch: __device__ globals (zero-initialized at module load; k_scalar
// restores the zero state each call so graph replays see identical state).
__device__ int   g_head[TBL_SIZE];     // bucket heads, 0 = empty, else occ+1
__device__ int   g_next[NOCC];         // links, 0 = end, else occ+1
__device__ float g_S0[B_N];            // per-sample scaled base sum
__device__ int   g_rcnt[B_N];          // interactions per later-sample b
__device__ int   g_ra[B_N * ROW_CAP];  // earlier sample index a
__device__ float g_rk[B_N * ROW_CAP];  // coefficient -LR * f^(-a)

__device__ __forceinline__ unsigned hash_idx(unsigned x) {
    x *= 2654435761u;
    x ^= x >> 15;
    return x & TBL_MASK;
}

// ---- pass 1: scaled base sums + hash-chain occurrences by index ------------
__global__ void k_gather(const int* __restrict__ xw,
                         const float* __restrict__ w,
                         const int* __restrict__ dtimes) {
    int e = blockIdx.x * blockDim.x + threadIdx.x;   // occurrence id
    if (e >= NOCC) return;
    int idx = xw[e];

    // scaled contribution  c = w * f^(-dt) = w * exp(dt * ln(1/f))
    float c = w[idx] * __expf((float)dtimes[idx] * LN_F);

    // 32 consecutive occurrences = half a sample: warp reduce, 1 atomic/warp
    float s = c;
    #pragma unroll
    for (int o = 16; o; o >>= 1) s += __shfl_xor_sync(0xffffffffu, s, o);
    if ((threadIdx.x & 31) == 0) atomicAdd(&g_S0[e >> 6], s);

    // chain insert, 0-sentinel encoding (occ+1)
    g_next[e] = atomicExch(&g_head[hash_idx((unsigned)idx)], e + 1);
}

// ---- pass 2: harvest cross-sample couplings into per-row slot lists --------
__global__ void k_pairs(const int* __restrict__ xw) {
    int e = blockIdx.x * blockDim.x + threadIdx.x;
    if (e >= NOCC) return;
    int idx = xw[e];
    int b   = e >> 6;
    for (int v = g_head[hash_idx((unsigned)idx)]; v; v = g_next[v - 1]) {
        int e2 = v - 1;
        int a  = e2 >> 6;
        if (a < b && xw[e2] == idx) {
            int pos = atomicAdd(&g_rcnt[b], 1);
            if (pos < ROW_CAP) {
                g_ra[b * ROW_CAP + pos] = a;
                g_rk[b * ROW_CAP + pos] = -LR_W * __expf((float)a * LN_F);
            }
        }
    }
}

// ---- pass 3: scalar recurrence + overlapped scratch cleanup ----------------
__global__ void __launch_bounds__(B_N, 1)
k_scalar(const float* __restrict__ y,
         const float* __restrict__ b_in,
         float* __restrict__ out) {
    __shared__ float sAh [B_N];    // 0.5 * S0[j] * f^j
    __shared__ float sD  [B_N];    // (sAh[j+1]-sAh[j]) - 0.0125*(1-2y[j])
    __shared__ float sHy [B_N];    // 0.5 - y[j]
    __shared__ float sFq [B_N];    // f^j (correction rows only)
    __shared__ float sG  [B_N];    // gradient history
    __shared__ int   sCnt[B_N];
    __shared__ int   sRows[B_N];   // ordered list of correction rows
    __shared__ int   sWoff[33];

    const int j    = threadIdx.x;
    const int wid  = j >> 5;
    const int lane = j & 31;

    // parallel preload
    float fq = __expf(-(float)j * LN_F);         // f^j
    float yj = y[j];
    float ah = 0.5f * (g_S0[j] * fq);
    sAh[j] = ah;
    sHy[j] = 0.5f - yj;
    sFq[j] = fq;
    int cnt = g_rcnt[j];
    sCnt[j] = cnt;
    unsigned m = __ballot_sync(0xffffffffu, cnt > 0);
    if (lane == 0) sWoff[wid] = __popc(m);
    __syncthreads();
    // sD needs sAh[j+1];  penalty = 0.0125*(1-2y) off-chain constant
    sD[j] = ((j < B_N - 1) ? (sAh[j + 1] - ah) : 0.0f)
            - 0.0125f * (1.0f - 2.0f * yj);
    if (j == 0) {
        int acc = 0;
        #pragma unroll
        for (int wq = 0; wq < 32; wq++) { int c = sWoff[wq]; sWoff[wq] = acc; acc += c; }
        sWoff[32] = acc;
    }
    __syncthreads();
    if (cnt > 0)
        sRows[sWoff[wid] + __popc(m & ((1u << lane) - 1u))] = j;
    __syncthreads();

    if (j >= 32) {
        // helper warps: restore scratch zero-state for the next graph replay
        // (g_S0 / g_rcnt already captured into smem; g_head done with;
        //  g_next fully rewritten by k_gather; g_ra/g_rk bounded by rcnt)
        int t = j - 32;                        // 0..991
        int4 z4 = make_int4(0, 0, 0, 0);
        int4* h4 = reinterpret_cast<int4*>(g_head);
        for (int v = t; v < TBL_SIZE / 4; v += 992) h4[v] = z4;
        if (t < B_N / 4) {
            reinterpret_cast<int4*>(g_rcnt)[t] = z4;
            reinterpret_cast<float4*>(g_S0)[t] = make_float4(0.f, 0.f, 0.f, 0.f);
        }
        return;
    }
    if (j != 0) return;

    // t = z/2 recurrence; chain per iter = tanh(16) + fma(4)
    const int nc = sWoff[32];
    float t = fmaf(0.5f, b_in[0], sAh[0]);
    int i = 0, ci = 0;
    for (;;) {
        int stop = (ci < nc) ? sRows[ci] : B_N;
        for (; i < stop; i++) {
            float th; asm("tanh.approx.f32 %0, %1;" : "=f"(th) : "f"(t));
            float c = t + sD[i];                      // parallel with tanh
            out[i] = fmaf(0.5f, th, 0.5f);            // p (off-chain)
            sG [i] = fmaf(0.5f, th, sHy[i]);          // g (off-chain)
            t = fmaf(-0.0125f, th, c);
        }
        if (i >= B_N) break;
        {   // correction row (rare): coupling affects z_i (and thus th_i)
            float corr = 0.0f;
            int n = sCnt[i]; if (n > ROW_CAP) n = ROW_CAP;
            int base = i * ROW_CAP;
            for (int r = 0; r < n; r++)
                corr += g_rk[base + r] * sG[g_ra[base + r]];
            float tc = fmaf(0.5f * sFq[i], corr, t);
            float th; asm("tanh.approx.f32 %0, %1;" : "=f"(th) : "f"(tc));
            out[i] = fmaf(0.5f, th, 0.5f);
            sG [i] = fmaf(0.5f, th, sHy[i]);
            // carry stays based on uncorrected sAh path + corrected th
            t = fmaf(-0.0125f, th, t + sD[i]);
            i++; ci++;
        }
    }
}

// ---------------------------------------------------------------------------
extern "C" void kernel_launch(void* const* d_in, const int* in_sizes, int n_in,
                              void* d_out, int out_size) {
    // metadata order: X_w_indices[65536], X_d[3072], y[1024], w[16777216],
    //                 b[1], decay_times[16777216]
    const int*   xw = nullptr;
    const float* y  = nullptr;
    const float* w  = nullptr;
    const float* b  = nullptr;
    const int*   dtimes = nullptr;
    int bigCount = 0;
    for (int i = 0; i < n_in; i++) {
        int sz = in_sizes[i];
        if      (sz == NOCC)     xw = (const int*)d_in[i];
        else if (sz == B_N)      y  = (const float*)d_in[i];
        else if (sz == 1)        b  = (const float*)d_in[i];
        else if (sz == D_SIZE) {
            if (bigCount++ == 0) w  = (const float*)d_in[i];
            else                 dtimes = (const int*)d_in[i];
        }
        // X_d (3072) unused by the wide forward pass
    }

    k_gather<<<NOCC / 256, 256>>>(xw, w, dtimes);
    k_pairs <<<NOCC / 256, 256>>>(xw);
    k_scalar<<<1, B_N>>>(y, b, (float*)d_out);
}

// round 17
// speedup vs baseline: 24.5424x; 3.6606x over previous
#include <cuda_runtime.h>

// ---------------------------------------------------------------------------
// WideDeep wide-side sequential SGD — interaction-factored, v6.
//
//   u = b/2 ;  u_{i+1} = u_i - LAM*tanh(sAh_i + cadd_i + u_i) - K_i
//   LAM = 0.0125, K_i = 0.0125*(1-2y_i), sAh_i = 0.5*S0_i*f^i
//   p_i = 0.5*th_i + 0.5 ;  g_i = 0.5*th_i + (0.5-y_i)
//
// v6: the 1024-step scalar recurrence is solved by parallel-in-time
// multiple shooting: 32 lanes x 32-step chunks, NPASS Newton passes.
// Each pass: lanes integrate chunks from boundary guesses (recording exit
// value F and derivative product F' = prod(1-LAM*(1-th^2)) ), thread 0
// propagates boundaries affinely, corr rows refresh their additive term
// from the latest gradient history. |F''|~0.3/chunk + initial boundary
// error ~0.3 -> errors 4e-2 / 8e-4 / 3e-7 / exact; NPASS=6 is margin.
// Transposed stride-33 smem layout keeps every LDS conflict-free.
// ---------------------------------------------------------------------------

#define D_SIZE    16777216
#define B_N       1024
#define F_N       64
#define NOCC      (B_N * F_N)          // 65536 occurrences
#define LR_W      0.05f
#define LAM       0.0125f              // 0.5 * 0.5 * LR
#define LN_F      1.0000005e-6f        // -ln(1 - 1e-6)
#define TBL_BITS  17
#define TBL_SIZE  (1 << TBL_BITS)
#define TBL_MASK  (TBL_SIZE - 1)
#define ROW_CAP   64                   // interaction slots per later-sample
#define NPASS     6

// Scratch: __device__ globals (zero at module load; k_scalar's helper warps
// restore the zero state each call so graph replays see identical state).
__device__ int   g_head[TBL_SIZE];     // bucket heads, 0 = empty, else occ+1
__device__ int   g_next[NOCC];         // links, 0 = end, else occ+1
__device__ float g_S0[B_N];            // per-sample scaled base sum
__device__ int   g_rcnt[B_N];          // interactions per later-sample b
__device__ int   g_ra[B_N * ROW_CAP];  // earlier sample index a
__device__ float g_rk[B_N * ROW_CAP];  // coefficient -LR * f^(-a)

__device__ __forceinline__ unsigned hash_idx(unsigned x) {
    x *= 2654435761u;
    x ^= x >> 15;
    return x & TBL_MASK;
}

// ---- pass 1: scaled base sums + hash-chain occurrences by index ------------
__global__ void k_gather(const int* __restrict__ xw,
                         const float* __restrict__ w,
                         const int* __restrict__ dtimes) {
    int e = blockIdx.x * blockDim.x + threadIdx.x;   // occurrence id
    if (e >= NOCC) return;
    int idx = xw[e];

    // scaled contribution  c = w * f^(-dt) = w * exp(dt * ln(1/f))
    float c = w[idx] * __expf((float)dtimes[idx] * LN_F);

    // 32 consecutive occurrences = half a sample: warp reduce, 1 atomic/warp
    float s = c;
    #pragma unroll
    for (int o = 16; o; o >>= 1) s += __shfl_xor_sync(0xffffffffu, s, o);
    if ((threadIdx.x & 31) == 0) atomicAdd(&g_S0[e >> 6], s);

    // chain insert, 0-sentinel encoding (occ+1)
    g_next[e] = atomicExch(&g_head[hash_idx((unsigned)idx)], e + 1);
}

// ---- pass 2: harvest cross-sample couplings into per-row slot lists --------
__global__ void k_pairs(const int* __restrict__ xw) {
    int e = blockIdx.x * blockDim.x + threadIdx.x;
    if (e >= NOCC) return;
    int idx = xw[e];
    int b   = e >> 6;
    for (int v = g_head[hash_idx((unsigned)idx)]; v; v = g_next[v - 1]) {
        int e2 = v - 1;
        int a  = e2 >> 6;
        if (a < b && xw[e2] == idx) {
            int pos = atomicAdd(&g_rcnt[b], 1);
            if (pos < ROW_CAP) {
                g_ra[b * ROW_CAP + pos] = a;
                g_rk[b * ROW_CAP + pos] = -LR_W * __expf((float)a * LN_F);
            }
        }
    }
}

// ---- pass 3: parallel-in-time shooting solve + overlapped cleanup ----------
// Row i = 32c+s lives at transposed smem position 33*s + c (conflict-free
// both for the preload write pattern and the warp-0 chunk walk).
__global__ void __launch_bounds__(B_N, 1)
k_scalar(const float* __restrict__ y,
         const float* __restrict__ b_in,
         float* __restrict__ out) {
    __shared__ float cAhT[33 * 32];    // sAh + corr-additive (refreshed/pass)
    __shared__ float sKT [33 * 32];    // 0.0125*(1-2y)
    __shared__ float sHyT[33 * 32];    // 0.5 - y
    __shared__ float sGT [33 * 32];    // gradient history (transposed)
    __shared__ float U[32], F[32], Fp[32];

    const int j   = threadIdx.x;
    const int c   = j >> 5;            // chunk of row j
    const int s   = j & 31;            // step of row j within its chunk
    const int pos = 33 * s + c;

    // ---- preload (all 1024 threads, thread j owns row j) ----
    float fq    = __expf(-(float)j * LN_F);        // f^j
    float yj    = y[j];
    float ah    = 0.5f * (g_S0[j] * fq);           // 0.5*S0*f^j
    float halfq = 0.5f * fq;
    cAhT[pos] = ah;
    sKT [pos] = LAM * (1.0f - 2.0f * yj);
    sHyT[pos] = 0.5f - yj;
    int cnt = g_rcnt[j];
    if (cnt > ROW_CAP) cnt = ROW_CAP;
    if (j < 32) U[j] = 0.5f * b_in[0];             // boundary guesses = u0
    __syncthreads();

    for (int pass = 0; pass < NPASS; ++pass) {
        if (c == 0) {
            // warp 0, lane j: integrate chunk j (rows 32j .. 32j+31)
            const int ln = j;
            float u  = U[ln];
            float dp = 1.0f;
            const bool last = (pass == NPASS - 1);
            #pragma unroll 8
            for (int stp = 0; stp < 32; ++stp) {
                int p2 = 33 * stp + ln;
                float tt = cAhT[p2] + u;                       // on-chain add
                float th; asm("tanh.approx.f32 %0, %1;" : "=f"(th) : "f"(tt));
                float uk = u - sKT[p2];                        // off-chain
                sGT[p2] = fmaf(0.5f, th, sHyT[p2]);            // g (off-chain)
                dp *= fmaf(LAM, th * th, 1.0f - LAM);          // F' (off-chain)
                if (last) out[ln * 32 + stp] = fmaf(0.5f, th, 0.5f);
                u = fmaf(-LAM, th, uk);                        // chain fma
            }
            F [ln] = u;
            Fp[ln] = dp;
        } else if (pass == 0) {
            // helper threads: restore scratch zero-state for next replay,
            // overlapped with warp 0's first integration pass
            int t = j - 32;                        // 0..991
            int4 z4 = make_int4(0, 0, 0, 0);
            int4* h4 = reinterpret_cast<int4*>(g_head);
            for (int v = t; v < TBL_SIZE / 4; v += 992) h4[v] = z4;
            if (t < B_N / 4) {
                reinterpret_cast<int4*>(g_rcnt)[t] = z4;
                reinterpret_cast<float4*>(g_S0)[t] = make_float4(0.f, 0.f, 0.f, 0.f);
            }
        }
        __syncthreads();

        if (pass < NPASS - 1) {
            // Newton boundary propagation: U_{c+1} <- F_c + F'_c (U_c - U_c^old)
            if (j == 0) {
                float unew = U[0];                 // u0 is exact, preserved
                #pragma unroll
                for (int cc = 0; cc < 32; ++cc) {
                    float uo = U[cc];
                    U[cc] = unew;
                    unew = fmaf(Fp[cc], unew - uo, F[cc]);
                }
            }
            // corr rows: refresh additive term from latest gradient history
            if (cnt > 0) {
                float corr = 0.0f;
                int base = j * ROW_CAP;
                for (int r = 0; r < cnt; ++r) {
                    int a = g_ra[base + r];
                    corr += g_rk[base + r] * sGT[33 * (a & 31) + (a >> 5)];
                }
                cAhT[pos] = fmaf(halfq, corr, ah);
            }
            __syncthreads();
        }
    }
}

// ---------------------------------------------------------------------------
extern "C" void kernel_launch(void* const* d_in, const int* in_sizes, int n_in,
                              void* d_out, int out_size) {
    // metadata order: X_w_indices[65536], X_d[3072], y[1024], w[16777216],
    //                 b[1], decay_times[16777216]
    const int*   xw = nullptr;
    const float* y  = nullptr;
    const float* w  = nullptr;
    const float* b  = nullptr;
    const int*   dtimes = nullptr;
    int bigCount = 0;
    for (int i = 0; i < n_in; i++) {
        int sz = in_sizes[i];
        if      (sz == NOCC)     xw = (const int*)d_in[i];
        else if (sz == B_N)      y  = (const float*)d_in[i];
        else if (sz == 1)        b  = (const float*)d_in[i];
        else if (sz == D_SIZE) {
            if (bigCount++ == 0) w  = (const float*)d_in[i];
            else                 dtimes = (const int*)d_in[i];
        }
        // X_d (3072) unused by the wide forward pass
    }

    k_gather<<<NOCC / 256, 256>>>(xw, w, dtimes);
    k_pairs <<<NOCC / 256, 256>>>(xw);
    k_scalar<<<1, B_N>>>(y, b, (float*)d_out);
}